// round 8
// baseline (speedup 1.0000x reference)
#include <cuda_runtime.h>
#include <cuda_bf16.h>
#include <cstdint>

#define B_SZ 2
#define T_SZ 4096
#define D_MODEL 1024
#define D_STATE 16
#define D_CONV 4
#define D_INNER 2048
#define DT_RANK 64
#define NTOK (B_SZ * T_SZ)              // 8192
#define XDBC_W (DT_RANK + 2 * D_STATE)  // 96

// ---------------- scratch (device globals; no allocation allowed) ----------
__device__ float g_xn[NTOK * D_MODEL];
__device__ float g_xr[NTOK * 2 * D_INNER];   // [u | silu(res)] after epilogue
__device__ float g_u[NTOK * D_INNER];
__device__ float g_xdbc[NTOK * XDBC_W];
__device__ float g_delta[NTOK * D_INNER];
__device__ float g_y[NTOK * D_INNER];

// ---------------- cp.async helpers -----------------------------------------
__device__ __forceinline__ void cpa16(uint32_t dst, const void* src) {
    asm volatile("cp.async.cg.shared.global [%0], [%1], 16;\n" ::"r"(dst), "l"(src));
}
__device__ __forceinline__ void cpa16_guard(uint32_t dst, const void* src, int sz) {
    asm volatile("cp.async.cg.shared.global [%0], [%1], 16, %2;\n"
                 ::"r"(dst), "l"(src), "r"(sz));
}
__device__ __forceinline__ void cpa_commit() {
    asm volatile("cp.async.commit_group;\n");
}
template <int N>
__device__ __forceinline__ void cpa_wait() {
    asm volatile("cp.async.wait_group %0;\n" ::"n"(N));
}

// ---------------- 1. RMSNorm -----------------------------------------------
__global__ void rmsnorm_kernel(const float* __restrict__ x,
                               const float* __restrict__ w) {
    int tok = blockIdx.x;
    const float* xp = x + (size_t)tok * D_MODEL;
    float s = 0.f;
    for (int i = threadIdx.x; i < D_MODEL; i += 256) {
        float v = xp[i];
        s += v * v;
    }
    __shared__ float red[8];
    #pragma unroll
    for (int o = 16; o > 0; o >>= 1) s += __shfl_down_sync(0xffffffffu, s, o);
    if ((threadIdx.x & 31) == 0) red[threadIdx.x >> 5] = s;
    __syncthreads();
    if (threadIdx.x < 8) {
        float v = red[threadIdx.x];
        #pragma unroll
        for (int o = 4; o > 0; o >>= 1) v += __shfl_down_sync(0xffu, v, o, 8);
        if (threadIdx.x == 0) red[0] = rsqrtf(v / (float)D_MODEL + 1e-5f);
    }
    __syncthreads();
    float rs = red[0];
    float* op = g_xn + (size_t)tok * D_MODEL;
    for (int i = threadIdx.x; i < D_MODEL; i += 256) op[i] = xp[i] * rs * w[i];
}

// ---------------- 2. 3-stage pipelined tf32 tensor-core GEMM ----------------
// C[M,N] = epi(A[M,K](lda) @ W[K,N]) (+resid). BM=BN=128, BK=32.
// EPI: 0 none, 1 silu for col>=N/2, 2 softplus+bias.
#define AS_STRIDE 36
#define BS_STRIDE 136
#define A_STAGE_F (128 * AS_STRIDE)
#define B_STAGE_F (32 * BS_STRIDE)
#define STAGE_F (A_STAGE_F + B_STAGE_F)           // 8960 floats / stage
#define GEMM_SMEM_BYTES (3 * STAGE_F * 4)         // 107520 B

template <bool NGUARD, int EPI>
__global__ __launch_bounds__(256, 2)
void gemm_tf32(const float* __restrict__ A, const float* __restrict__ W,
               const float* __restrict__ resid, const float* __restrict__ bias,
               float* __restrict__ C, int M, int N, int K, int lda) {
    extern __shared__ float smem[];
    int tid = threadIdx.x;
    int lane = tid & 31, warp = tid >> 5;
    int wm = warp & 1, wn = warp >> 1;
    int bm = blockIdx.y * 128, bn = blockIdx.x * 128;
    int t4 = lane >> 2, tm = lane & 3;
    float acc[4][4][4];
    #pragma unroll
    for (int i = 0; i < 4; i++)
        #pragma unroll
        for (int j = 0; j < 4; j++)
            #pragma unroll
            for (int r = 0; r < 4; r++) acc[i][j][r] = 0.f;

    int ar = tid >> 3, ac = (tid & 7) << 2;
    int br = tid >> 5, bc = (tid & 31) << 2;

    int nt = K >> 5;

    auto issue = [&](int c, int buf) {
        float* pA = smem + buf * STAGE_F;
        float* pB = pA + A_STAGE_F;
        int k0 = c << 5;
        #pragma unroll
        for (int p = 0; p < 4; ++p) {
            int r = ar + p * 32;
            cpa16((uint32_t)__cvta_generic_to_shared(pA + r * AS_STRIDE + ac),
                  A + (size_t)(bm + r) * lda + k0 + ac);
        }
        #pragma unroll
        for (int p = 0; p < 4; ++p) {
            int r = br + p * 8;
            const float* src = W + (size_t)(k0 + r) * N + bn + bc;
            uint32_t dst = (uint32_t)__cvta_generic_to_shared(pB + r * BS_STRIDE + bc);
            if (NGUARD)
                cpa16_guard(dst, src, (bn + bc < N) ? 16 : 0);
            else
                cpa16(dst, src);
        }
        cpa_commit();
    };

    issue(0, 0);
    if (nt > 1) issue(1, 1);

    for (int c = 0; c < nt; ++c) {
        int buf = c % 3;
        if (c < nt - 1)
            cpa_wait<1>();   // stage c complete, stage c+1 still in flight
        else
            cpa_wait<0>();
        __syncthreads();     // publish stage c; retire compute on buf (c+2)%3
        if (c + 2 < nt) issue(c + 2, (c + 2) % 3);

        float* pA = smem + buf * STAGE_F;
        float* pB = pA + A_STAGE_F;
        #pragma unroll
        for (int ks = 0; ks < 4; ++ks) {
            int kb = ks * 8;
            uint32_t af[4][4], bf[4][2];
            #pragma unroll
            for (int im = 0; im < 4; im++) {
                int rb = wm * 64 + im * 16 + t4;
                af[im][0] = __float_as_uint(pA[rb * AS_STRIDE + kb + tm]);
                af[im][1] = __float_as_uint(pA[(rb + 8) * AS_STRIDE + kb + tm]);
                af[im][2] = __float_as_uint(pA[rb * AS_STRIDE + kb + tm + 4]);
                af[im][3] = __float_as_uint(pA[(rb + 8) * AS_STRIDE + kb + tm + 4]);
            }
            #pragma unroll
            for (int jn = 0; jn < 4; jn++) {
                int cb = wn * 32 + jn * 8 + t4;
                bf[jn][0] = __float_as_uint(pB[(kb + tm) * BS_STRIDE + cb]);
                bf[jn][1] = __float_as_uint(pB[(kb + tm + 4) * BS_STRIDE + cb]);
            }
            #pragma unroll
            for (int im = 0; im < 4; im++)
                #pragma unroll
                for (int jn = 0; jn < 4; jn++)
                    asm volatile(
                        "mma.sync.aligned.m16n8k8.row.col.f32.tf32.tf32.f32 "
                        "{%0,%1,%2,%3}, {%4,%5,%6,%7}, {%8,%9}, {%0,%1,%2,%3};\n"
                        : "+f"(acc[im][jn][0]), "+f"(acc[im][jn][1]),
                          "+f"(acc[im][jn][2]), "+f"(acc[im][jn][3])
                        : "r"(af[im][0]), "r"(af[im][1]),
                          "r"(af[im][2]), "r"(af[im][3]),
                          "r"(bf[jn][0]), "r"(bf[jn][1]));
        }
    }

    int half = N >> 1;
    #pragma unroll
    for (int im = 0; im < 4; im++) {
        int row = bm + wm * 64 + im * 16 + t4;
        #pragma unroll
        for (int jn = 0; jn < 4; jn++) {
            int col = bn + wn * 32 + jn * 8 + 2 * tm;
            if (NGUARD && col >= N) continue;
            size_t o0 = (size_t)row * N + col;
            size_t o1 = (size_t)(row + 8) * N + col;
            float v[4] = {acc[im][jn][0], acc[im][jn][1],
                          acc[im][jn][2], acc[im][jn][3]};
            if (EPI == 2) {
                float b0 = bias[col], b1 = bias[col + 1];
                v[0] += b0; v[1] += b1; v[2] += b0; v[3] += b1;
                #pragma unroll
                for (int e = 0; e < 4; e++)
                    v[e] = (v[e] > 20.f) ? v[e] : log1pf(__expf(v[e]));
            } else if (EPI == 1) {
                if (col >= half) {
                    #pragma unroll
                    for (int e = 0; e < 4; e++)
                        v[e] = v[e] / (1.f + __expf(-v[e]));
                }
            }
            float2 v0 = make_float2(v[0], v[1]);
            float2 v1 = make_float2(v[2], v[3]);
            if (resid) {
                float2 r0 = *(const float2*)(resid + o0);
                float2 r1 = *(const float2*)(resid + o1);
                v0.x += r0.x; v0.y += r0.y;
                v1.x += r1.x; v1.y += r1.y;
            }
            *(float2*)(C + o0) = v0;
            *(float2*)(C + o1) = v1;
        }
    }
}

// ---------------- 3. depthwise causal conv (K=4) + bias + SiLU -------------
__global__ void conv_silu_kernel(const float* __restrict__ cw,
                                 const float* __restrict__ cb) {
    int idx = blockIdx.x * blockDim.x + threadIdx.x;
    if (idx >= NTOK * D_INNER) return;
    int d = idx & (D_INNER - 1);
    int tok = idx >> 11;
    int t = tok & (T_SZ - 1);
    float acc = cb[d];
    #pragma unroll
    for (int k = 0; k < D_CONV; ++k) {
        int tt = t - (D_CONV - 1) + k;
        if (tt >= 0)
            acc = fmaf(g_xr[(size_t)(tok - (D_CONV - 1) + k) * (2 * D_INNER) + d],
                       cw[d * D_CONV + k], acc);
    }
    g_u[idx] = acc / (1.f + __expf(-acc));
}

// ---------------- 6. smem-staged selective scan (res pre-silued) ------------
#define SCAN_TC 32
#define SCAN_CH 32
#define SCAN_NC (T_SZ / SCAN_TC)

__global__ __launch_bounds__(512, 1)
void scan_kernel(const float* __restrict__ A_log, const float* __restrict__ Dp) {
    __shared__ float sD[2][SCAN_TC][SCAN_CH];
    __shared__ float sU[2][SCAN_TC][SCAN_CH];
    __shared__ float sR[2][SCAN_TC][SCAN_CH];
    __shared__ float sBC[2][SCAN_TC][32];
    __shared__ float sY[SCAN_TC][SCAN_CH];

    int tid = threadIdx.x;
    int bb = blockIdx.x >> 6;
    int d0 = (blockIdx.x & 63) * SCAN_CH;
    size_t tokbase = (size_t)bb * T_SZ;

    int lidx = tid & 255;
    int li = lidx >> 3;
    int lj = (lidx & 7) << 2;
    int lgrp = tid >> 8;

    int warp = tid >> 5, lane = tid & 31;
    int ch = warp * 2 + (lane >> 4);
    int n = lane & 15;
    int dg = d0 + ch;
    float a = -__expf(A_log[dg * D_STATE + n]);
    float Dv = Dp[dg];
    float h = 0.f;

    auto issue_chunk = [&](int c, int buf) {
        size_t tok = tokbase + (size_t)c * SCAN_TC + li;
        if (lgrp == 0) {
            cpa16((uint32_t)__cvta_generic_to_shared(&sD[buf][li][lj]),
                  g_delta + tok * D_INNER + d0 + lj);
            cpa16((uint32_t)__cvta_generic_to_shared(&sU[buf][li][lj]),
                  g_u + tok * D_INNER + d0 + lj);
        } else {
            cpa16((uint32_t)__cvta_generic_to_shared(&sR[buf][li][lj]),
                  g_xr + tok * (2 * D_INNER) + D_INNER + d0 + lj);
            cpa16((uint32_t)__cvta_generic_to_shared(&sBC[buf][li][lj]),
                  g_xdbc + tok * XDBC_W + DT_RANK + lj);
        }
        cpa_commit();
    };

    issue_chunk(0, 0);

    for (int c = 0; c < SCAN_NC; ++c) {
        int buf = c & 1;
        if (c + 1 < SCAN_NC) {
            issue_chunk(c + 1, buf ^ 1);
            cpa_wait<1>();
        } else {
            cpa_wait<0>();
        }
        __syncthreads();

        #pragma unroll 4
        for (int t = 0; t < SCAN_TC; ++t) {
            float dv = sD[buf][t][ch];
            float uv = sU[buf][t][ch];
            float Bv = sBC[buf][t][n];
            float Cv = sBC[buf][t][16 + n];
            h = fmaf(__expf(dv * a), h, (dv * uv) * Bv);
            float p = h * Cv;
            p += __shfl_down_sync(0xffffffffu, p, 8, 16);
            p += __shfl_down_sync(0xffffffffu, p, 4, 16);
            p += __shfl_down_sync(0xffffffffu, p, 2, 16);
            p += __shfl_down_sync(0xffffffffu, p, 1, 16);
            if (n == 0) {
                sY[t][ch] = fmaf(uv, Dv, p) * sR[buf][t][ch];
            }
        }
        __syncthreads();

        if (lgrp == 0) {
            size_t tok = tokbase + (size_t)c * SCAN_TC + li;
            *(float4*)(g_y + tok * D_INNER + d0 + lj) = *(float4*)(&sY[li][lj]);
        }
    }
}

// ---------------- launch ----------------------------------------------------
extern "C" void kernel_launch(void* const* d_in, const int* in_sizes, int n_in,
                              void* d_out, int out_size) {
    const float* x      = (const float*)d_in[0];
    const float* norm_w = (const float*)d_in[1];
    const float* w_in   = (const float*)d_in[2];
    const float* conv_w = (const float*)d_in[3];
    const float* conv_b = (const float*)d_in[4];
    const float* w_x    = (const float*)d_in[5];
    const float* w_dt   = (const float*)d_in[6];
    const float* b_dt   = (const float*)d_in[7];
    const float* A_log  = (const float*)d_in[8];
    const float* Dp     = (const float*)d_in[9];
    const float* w_out  = (const float*)d_in[10];
    float* out = (float*)d_out;

    void *p_xn = nullptr, *p_xr = nullptr, *p_u = nullptr, *p_xdbc = nullptr,
         *p_delta = nullptr, *p_y = nullptr;
    cudaGetSymbolAddress(&p_xn, g_xn);
    cudaGetSymbolAddress(&p_xr, g_xr);
    cudaGetSymbolAddress(&p_u, g_u);
    cudaGetSymbolAddress(&p_xdbc, g_xdbc);
    cudaGetSymbolAddress(&p_delta, g_delta);
    cudaGetSymbolAddress(&p_y, g_y);

    cudaFuncSetAttribute(gemm_tf32<false, 0>,
                         cudaFuncAttributeMaxDynamicSharedMemorySize, GEMM_SMEM_BYTES);
    cudaFuncSetAttribute(gemm_tf32<false, 1>,
                         cudaFuncAttributeMaxDynamicSharedMemorySize, GEMM_SMEM_BYTES);
    cudaFuncSetAttribute(gemm_tf32<false, 2>,
                         cudaFuncAttributeMaxDynamicSharedMemorySize, GEMM_SMEM_BYTES);
    cudaFuncSetAttribute(gemm_tf32<true, 0>,
                         cudaFuncAttributeMaxDynamicSharedMemorySize, GEMM_SMEM_BYTES);

    rmsnorm_kernel<<<NTOK, 256>>>(x, norm_w);

    // xr = xn @ w_in; silu applied to res half (cols >= 2048)
    gemm_tf32<false, 1><<<dim3(2 * D_INNER / 128, NTOK / 128), 256, GEMM_SMEM_BYTES>>>(
        (const float*)p_xn, w_in, nullptr, nullptr, (float*)p_xr,
        NTOK, 2 * D_INNER, D_MODEL, D_MODEL);

    conv_silu_kernel<<<(NTOK * D_INNER + 255) / 256, 256>>>(conv_w, conv_b);

    // xdbc = u @ w_x  (8192 x 96, K=2048)
    gemm_tf32<true, 0><<<dim3(1, NTOK / 128), 256, GEMM_SMEM_BYTES>>>(
        (const float*)p_u, w_x, nullptr, nullptr, (float*)p_xdbc,
        NTOK, XDBC_W, D_INNER, D_INNER);

    // delta = softplus(dt @ w_dt + b_dt)  (8192 x 2048, K=64, A lda=96)
    gemm_tf32<false, 2><<<dim3(D_INNER / 128, NTOK / 128), 256, GEMM_SMEM_BYTES>>>(
        (const float*)p_xdbc, w_dt, nullptr, b_dt, (float*)p_delta,
        NTOK, D_INNER, DT_RANK, XDBC_W);

    scan_kernel<<<B_SZ * D_INNER / SCAN_CH, 512>>>(A_log, Dp);

    // out = y @ w_out + x  (8192 x 1024, K=2048)
    gemm_tf32<false, 0><<<dim3(D_MODEL / 128, NTOK / 128), 256, GEMM_SMEM_BYTES>>>(
        (const float*)p_y, w_out, x, nullptr, out, NTOK, D_MODEL, D_INNER, D_INNER);
}

// round 9
// speedup vs baseline: 1.1729x; 1.1729x over previous
#include <cuda_runtime.h>
#include <cuda_fp16.h>
#include <cstdint>

#define B_SZ 2
#define T_SZ 4096
#define D_MODEL 1024
#define D_STATE 16
#define D_CONV 4
#define D_INNER 2048
#define DT_RANK 64
#define NTOK (B_SZ * T_SZ)              // 8192
#define XDBC_W (DT_RANK + 2 * D_STATE)  // 96

// ---------------- scratch (device globals; no allocation allowed) ----------
__device__ __half g_xn_h[NTOK * D_MODEL];
__device__ float  g_xr[NTOK * 2 * D_INNER];      // [u | silu(res)]
__device__ float  g_u[NTOK * D_INNER];
__device__ __half g_u_h[NTOK * D_INNER];
__device__ float  g_xdbc[NTOK * XDBC_W];
__device__ __half g_xdbc_h[NTOK * XDBC_W];
__device__ float  g_delta[NTOK * D_INNER];
__device__ __half g_y_h[NTOK * D_INNER];
// transposed fp16 weights  Wt[n][k]
__device__ __half g_winT[2 * D_INNER * D_MODEL];     // [4096][1024]
__device__ __half g_wxT[128 * D_INNER];              // [128(pad 96)][2048]
__device__ __half g_wdtT[D_INNER * DT_RANK];         // [2048][64]
__device__ __half g_woutT[D_MODEL * D_INNER];        // [1024][2048]

// ---------------- cp.async helpers -----------------------------------------
__device__ __forceinline__ void cpa16(uint32_t dst, const void* src) {
    asm volatile("cp.async.cg.shared.global [%0], [%1], 16;\n" ::"r"(dst), "l"(src));
}
__device__ __forceinline__ void cpa_commit() {
    asm volatile("cp.async.commit_group;\n");
}
template <int N>
__device__ __forceinline__ void cpa_wait() {
    asm volatile("cp.async.wait_group %0;\n" ::"n"(N));
}

// ---------------- 0. weight convert + transpose to fp16 --------------------
// in: fp32 [K][N]; out: fp16 [Npad][K] (rows >= N zero-filled)
__global__ void transpose_h(const float* __restrict__ in, __half* __restrict__ out,
                            int K, int N) {
    __shared__ float t[32][33];
    int n0 = blockIdx.x * 32, k0 = blockIdx.y * 32;
    int tx = threadIdx.x, ty = threadIdx.y;       // 32 x 8
    #pragma unroll
    for (int r = 0; r < 4; ++r) {
        int n = n0 + tx;
        t[ty + r * 8][tx] = (n < N) ? in[(size_t)(k0 + ty + r * 8) * N + n] : 0.f;
    }
    __syncthreads();
    #pragma unroll
    for (int r = 0; r < 4; ++r)
        out[(size_t)(n0 + ty + r * 8) * K + k0 + tx] = __float2half(t[tx][ty + r * 8]);
}

// ---------------- 1. RMSNorm (writes fp16 A for GEMM1) ----------------------
__global__ void rmsnorm_kernel(const float* __restrict__ x,
                               const float* __restrict__ w) {
    int tok = blockIdx.x;
    const float* xp = x + (size_t)tok * D_MODEL;
    float s = 0.f;
    for (int i = threadIdx.x; i < D_MODEL; i += 256) {
        float v = xp[i];
        s += v * v;
    }
    __shared__ float red[8];
    #pragma unroll
    for (int o = 16; o > 0; o >>= 1) s += __shfl_down_sync(0xffffffffu, s, o);
    if ((threadIdx.x & 31) == 0) red[threadIdx.x >> 5] = s;
    __syncthreads();
    if (threadIdx.x < 8) {
        float v = red[threadIdx.x];
        #pragma unroll
        for (int o = 4; o > 0; o >>= 1) v += __shfl_down_sync(0xffu, v, o, 8);
        if (threadIdx.x == 0) red[0] = rsqrtf(v / (float)D_MODEL + 1e-5f);
    }
    __syncthreads();
    float rs = red[0];
    __half* op = g_xn_h + (size_t)tok * D_MODEL;
    for (int i = threadIdx.x; i < D_MODEL; i += 256)
        op[i] = __float2half(xp[i] * rs * w[i]);
}

// ---------------- 2. fp16 tensor-core GEMM (m16n8k16, fp32 acc) -------------
// C[M,N] = epi(A[M,K](lda,fp16) @ Wt[N][K](fp16)) (+resid)
// BM=BN=128, BK=32, 2-stage cp.async double buffer. 8 warps (2x4), warp 64x32.
// EPI: 0 none, 1 silu col>=N/2, 2 softplus+bias.  WH: also store fp16 copy.
#define HA 40   // half stride per smem row (80B: 16B-multiple, conflict-free)

template <bool NGUARD, int EPI, bool WH>
__global__ __launch_bounds__(256, 2)
void gemm_h16(const __half* __restrict__ A, const __half* __restrict__ Wt,
              const float* __restrict__ resid, const float* __restrict__ bias,
              float* __restrict__ C, __half* __restrict__ Ch,
              int M, int N, int K, int lda) {
    __shared__ __align__(16) __half As[2][128][HA];
    __shared__ __align__(16) __half Bs[2][128][HA];
    int tid = threadIdx.x;
    int lane = tid & 31, warp = tid >> 5;
    int wm = warp & 1, wn = warp >> 1;
    int bm = blockIdx.y * 128, bn = blockIdx.x * 128;
    int t4 = lane >> 2, tm = lane & 3;
    float acc[4][4][4];
    #pragma unroll
    for (int i = 0; i < 4; i++)
        #pragma unroll
        for (int j = 0; j < 4; j++)
            #pragma unroll
            for (int r = 0; r < 4; r++) acc[i][j][r] = 0.f;

    int nt = K >> 5;

    auto issue = [&](int c, int buf) {
        int k0 = c << 5;
        #pragma unroll
        for (int i = 0; i < 2; ++i) {
            int id = tid + i * 256;
            int row = id >> 2, cc = (id & 3) << 3;        // 4 chunks of 8 halves
            cpa16((uint32_t)__cvta_generic_to_shared(&As[buf][row][cc]),
                  A + (size_t)(bm + row) * lda + k0 + cc);
            cpa16((uint32_t)__cvta_generic_to_shared(&Bs[buf][row][cc]),
                  Wt + (size_t)(bn + row) * K + k0 + cc);
        }
        cpa_commit();
    };

    issue(0, 0);

    for (int c = 0; c < nt; ++c) {
        int buf = c & 1;
        cpa_wait<0>();
        __syncthreads();                 // stage c visible; prev compute retired
        if (c + 1 < nt) issue(c + 1, buf ^ 1);

        #pragma unroll
        for (int ks = 0; ks < 2; ++ks) {
            int kb = ks * 16;
            uint32_t af[4][4], bf[4][2];
            #pragma unroll
            for (int im = 0; im < 4; im++) {
                int rb = wm * 64 + im * 16 + t4;
                af[im][0] = *(const uint32_t*)&As[buf][rb][kb + 2 * tm];
                af[im][1] = *(const uint32_t*)&As[buf][rb + 8][kb + 2 * tm];
                af[im][2] = *(const uint32_t*)&As[buf][rb][kb + 2 * tm + 8];
                af[im][3] = *(const uint32_t*)&As[buf][rb + 8][kb + 2 * tm + 8];
            }
            #pragma unroll
            for (int jn = 0; jn < 4; jn++) {
                int cb = wn * 32 + jn * 8 + t4;
                bf[jn][0] = *(const uint32_t*)&Bs[buf][cb][kb + 2 * tm];
                bf[jn][1] = *(const uint32_t*)&Bs[buf][cb][kb + 2 * tm + 8];
            }
            #pragma unroll
            for (int im = 0; im < 4; im++)
                #pragma unroll
                for (int jn = 0; jn < 4; jn++)
                    asm volatile(
                        "mma.sync.aligned.m16n8k16.row.col.f32.f16.f16.f32 "
                        "{%0,%1,%2,%3}, {%4,%5,%6,%7}, {%8,%9}, {%0,%1,%2,%3};\n"
                        : "+f"(acc[im][jn][0]), "+f"(acc[im][jn][1]),
                          "+f"(acc[im][jn][2]), "+f"(acc[im][jn][3])
                        : "r"(af[im][0]), "r"(af[im][1]),
                          "r"(af[im][2]), "r"(af[im][3]),
                          "r"(bf[jn][0]), "r"(bf[jn][1]));
        }
    }

    int half_n = N >> 1;
    #pragma unroll
    for (int im = 0; im < 4; im++) {
        int row = bm + wm * 64 + im * 16 + t4;
        #pragma unroll
        for (int jn = 0; jn < 4; jn++) {
            int col = bn + wn * 32 + jn * 8 + 2 * tm;
            if (NGUARD && col >= N) continue;
            size_t o0 = (size_t)row * N + col;
            size_t o1 = (size_t)(row + 8) * N + col;
            float v[4] = {acc[im][jn][0], acc[im][jn][1],
                          acc[im][jn][2], acc[im][jn][3]};
            if (EPI == 2) {
                float b0 = bias[col], b1 = bias[col + 1];
                v[0] += b0; v[1] += b1; v[2] += b0; v[3] += b1;
                #pragma unroll
                for (int e = 0; e < 4; e++)
                    v[e] = (v[e] > 20.f) ? v[e] : log1pf(__expf(v[e]));
            } else if (EPI == 1) {
                if (col >= half_n) {
                    #pragma unroll
                    for (int e = 0; e < 4; e++)
                        v[e] = v[e] / (1.f + __expf(-v[e]));
                }
            }
            float2 v0 = make_float2(v[0], v[1]);
            float2 v1 = make_float2(v[2], v[3]);
            if (resid) {
                float2 r0 = *(const float2*)(resid + o0);
                float2 r1 = *(const float2*)(resid + o1);
                v0.x += r0.x; v0.y += r0.y;
                v1.x += r1.x; v1.y += r1.y;
            }
            *(float2*)(C + o0) = v0;
            *(float2*)(C + o1) = v1;
            if (WH) {
                *(__half2*)(Ch + o0) = __floats2half2_rn(v0.x, v0.y);
                *(__half2*)(Ch + o1) = __floats2half2_rn(v1.x, v1.y);
            }
        }
    }
}

// ---------------- 3. depthwise causal conv + bias + SiLU (fp32 + fp16 out) --
__global__ void conv_silu_kernel(const float* __restrict__ cw,
                                 const float* __restrict__ cb) {
    int idx = blockIdx.x * blockDim.x + threadIdx.x;
    if (idx >= NTOK * D_INNER) return;
    int d = idx & (D_INNER - 1);
    int tok = idx >> 11;
    int t = tok & (T_SZ - 1);
    float acc = cb[d];
    #pragma unroll
    for (int k = 0; k < D_CONV; ++k) {
        int tt = t - (D_CONV - 1) + k;
        if (tt >= 0)
            acc = fmaf(g_xr[(size_t)(tok - (D_CONV - 1) + k) * (2 * D_INNER) + d],
                       cw[d * D_CONV + k], acc);
    }
    float u = acc / (1.f + __expf(-acc));
    g_u[idx] = u;
    g_u_h[idx] = __float2half(u);
}

// ---------------- 6. smem-staged selective scan (res pre-silued) ------------
#define SCAN_TC 32
#define SCAN_CH 32
#define SCAN_NC (T_SZ / SCAN_TC)

__global__ __launch_bounds__(512, 1)
void scan_kernel(const float* __restrict__ A_log, const float* __restrict__ Dp) {
    __shared__ float sD[2][SCAN_TC][SCAN_CH];
    __shared__ float sU[2][SCAN_TC][SCAN_CH];
    __shared__ float sR[2][SCAN_TC][SCAN_CH];
    __shared__ float sBC[2][SCAN_TC][32];
    __shared__ float sY[SCAN_TC][SCAN_CH];

    int tid = threadIdx.x;
    int bb = blockIdx.x >> 6;
    int d0 = (blockIdx.x & 63) * SCAN_CH;
    size_t tokbase = (size_t)bb * T_SZ;

    int lidx = tid & 255;
    int li = lidx >> 3;
    int lj = (lidx & 7) << 2;
    int lgrp = tid >> 8;

    int warp = tid >> 5, lane = tid & 31;
    int ch = warp * 2 + (lane >> 4);
    int n = lane & 15;
    int dg = d0 + ch;
    float a = -__expf(A_log[dg * D_STATE + n]);
    float Dv = Dp[dg];
    float h = 0.f;

    auto issue_chunk = [&](int c, int buf) {
        size_t tok = tokbase + (size_t)c * SCAN_TC + li;
        if (lgrp == 0) {
            cpa16((uint32_t)__cvta_generic_to_shared(&sD[buf][li][lj]),
                  g_delta + tok * D_INNER + d0 + lj);
            cpa16((uint32_t)__cvta_generic_to_shared(&sU[buf][li][lj]),
                  g_u + tok * D_INNER + d0 + lj);
        } else {
            cpa16((uint32_t)__cvta_generic_to_shared(&sR[buf][li][lj]),
                  g_xr + tok * (2 * D_INNER) + D_INNER + d0 + lj);
            cpa16((uint32_t)__cvta_generic_to_shared(&sBC[buf][li][lj]),
                  g_xdbc + tok * XDBC_W + DT_RANK + lj);
        }
        cpa_commit();
    };

    issue_chunk(0, 0);

    for (int c = 0; c < SCAN_NC; ++c) {
        int buf = c & 1;
        if (c + 1 < SCAN_NC) {
            issue_chunk(c + 1, buf ^ 1);
            cpa_wait<1>();
        } else {
            cpa_wait<0>();
        }
        __syncthreads();

        #pragma unroll 4
        for (int t = 0; t < SCAN_TC; ++t) {
            float dv = sD[buf][t][ch];
            float uv = sU[buf][t][ch];
            float Bv = sBC[buf][t][n];
            float Cv = sBC[buf][t][16 + n];
            h = fmaf(__expf(dv * a), h, (dv * uv) * Bv);
            float p = h * Cv;
            p += __shfl_down_sync(0xffffffffu, p, 8, 16);
            p += __shfl_down_sync(0xffffffffu, p, 4, 16);
            p += __shfl_down_sync(0xffffffffu, p, 2, 16);
            p += __shfl_down_sync(0xffffffffu, p, 1, 16);
            if (n == 0) {
                sY[t][ch] = fmaf(uv, Dv, p) * sR[buf][t][ch];
            }
        }
        __syncthreads();

        if (lgrp == 0) {
            size_t tok = tokbase + (size_t)c * SCAN_TC + li;
            float4 v = *(float4*)(&sY[li][lj]);
            __half* dst = g_y_h + tok * D_INNER + d0 + lj;
            *(__half2*)(dst) = __floats2half2_rn(v.x, v.y);
            *(__half2*)(dst + 2) = __floats2half2_rn(v.z, v.w);
        }
    }
}

// ---------------- launch ----------------------------------------------------
extern "C" void kernel_launch(void* const* d_in, const int* in_sizes, int n_in,
                              void* d_out, int out_size) {
    const float* x      = (const float*)d_in[0];
    const float* norm_w = (const float*)d_in[1];
    const float* w_in   = (const float*)d_in[2];
    const float* conv_w = (const float*)d_in[3];
    const float* conv_b = (const float*)d_in[4];
    const float* w_x    = (const float*)d_in[5];
    const float* w_dt   = (const float*)d_in[6];
    const float* b_dt   = (const float*)d_in[7];
    const float* A_log  = (const float*)d_in[8];
    const float* Dp     = (const float*)d_in[9];
    const float* w_out  = (const float*)d_in[10];
    float* out = (float*)d_out;

    void *p_xn_h, *p_xr, *p_u_h, *p_xdbc, *p_xdbc_h, *p_delta, *p_y_h;
    void *p_winT, *p_wxT, *p_wdtT, *p_woutT;
    cudaGetSymbolAddress(&p_xn_h, g_xn_h);
    cudaGetSymbolAddress(&p_xr, g_xr);
    cudaGetSymbolAddress(&p_u_h, g_u_h);
    cudaGetSymbolAddress(&p_xdbc, g_xdbc);
    cudaGetSymbolAddress(&p_xdbc_h, g_xdbc_h);
    cudaGetSymbolAddress(&p_delta, g_delta);
    cudaGetSymbolAddress(&p_y_h, g_y_h);
    cudaGetSymbolAddress(&p_winT, g_winT);
    cudaGetSymbolAddress(&p_wxT, g_wxT);
    cudaGetSymbolAddress(&p_wdtT, g_wdtT);
    cudaGetSymbolAddress(&p_woutT, g_woutT);

    dim3 tb(32, 8);
    // weight convert+transpose (fp32 [K][N] -> fp16 [Npad][K])
    transpose_h<<<dim3(2 * D_INNER / 32, D_MODEL / 32), tb>>>(
        w_in, (__half*)p_winT, D_MODEL, 2 * D_INNER);
    transpose_h<<<dim3(128 / 32, D_INNER / 32), tb>>>(
        w_x, (__half*)p_wxT, D_INNER, XDBC_W);
    transpose_h<<<dim3(D_INNER / 32, DT_RANK / 32), tb>>>(
        w_dt, (__half*)p_wdtT, DT_RANK, D_INNER);
    transpose_h<<<dim3(D_MODEL / 32, D_INNER / 32), tb>>>(
        w_out, (__half*)p_woutT, D_INNER, D_MODEL);

    rmsnorm_kernel<<<NTOK, 256>>>(x, norm_w);

    // xr = xn @ w_in ; silu on res half
    gemm_h16<false, 1, false><<<dim3(2 * D_INNER / 128, NTOK / 128), 256>>>(
        (const __half*)p_xn_h, (const __half*)p_winT, nullptr, nullptr,
        (float*)p_xr, nullptr, NTOK, 2 * D_INNER, D_MODEL, D_MODEL);

    conv_silu_kernel<<<(NTOK * D_INNER + 255) / 256, 256>>>(conv_w, conv_b);

    // xdbc = u @ w_x  (N=96, store fp32 + fp16)
    gemm_h16<true, 0, true><<<dim3(1, NTOK / 128), 256>>>(
        (const __half*)p_u_h, (const __half*)p_wxT, nullptr, nullptr,
        (float*)p_xdbc, (__half*)p_xdbc_h, NTOK, XDBC_W, D_INNER, D_INNER);

    // delta = softplus(dt @ w_dt + b_dt)  (K=64, A lda=96)
    gemm_h16<false, 2, false><<<dim3(D_INNER / 128, NTOK / 128), 256>>>(
        (const __half*)p_xdbc_h, (const __half*)p_wdtT, nullptr, b_dt,
        (float*)p_delta, nullptr, NTOK, D_INNER, DT_RANK, XDBC_W);

    scan_kernel<<<B_SZ * D_INNER / SCAN_CH, 512>>>(A_log, Dp);

    // out = y @ w_out + x
    gemm_h16<false, 0, false><<<dim3(D_MODEL / 128, NTOK / 128), 256>>>(
        (const __half*)p_y_h, (const __half*)p_woutT, x, nullptr,
        out, nullptr, NTOK, D_MODEL, D_INNER, D_INNER);
}

// round 11
// speedup vs baseline: 1.2361x; 1.0539x over previous
#include <cuda_runtime.h>
#include <cuda_fp16.h>
#include <cstdint>

#define B_SZ 2
#define T_SZ 4096
#define D_MODEL 1024
#define D_STATE 16
#define D_CONV 4
#define D_INNER 2048
#define DT_RANK 64
#define NTOK (B_SZ * T_SZ)              // 8192
#define XDBC_W (DT_RANK + 2 * D_STATE)  // 96

// ---------------- scratch (device globals; no allocation allowed) ----------
__device__ __half g_xn_h[NTOK * D_MODEL];
__device__ float  g_xr[NTOK * 2 * D_INNER];      // [u | silu(res)]
__device__ float  g_u[NTOK * D_INNER];
__device__ __half g_u_h[NTOK * D_INNER];
__device__ float  g_xdbc[NTOK * XDBC_W];
__device__ __half g_xdbc_h[NTOK * XDBC_W];
__device__ float  g_delta[NTOK * D_INNER];
__device__ __half g_y_h[NTOK * D_INNER];
// transposed fp16 weights  Wt[n][k]
__device__ __half g_winT[2 * D_INNER * D_MODEL];     // [4096][1024]
__device__ __half g_wxT[128 * D_INNER];              // [128(pad 96)][2048]
__device__ __half g_wdtT[D_INNER * DT_RANK];         // [2048][64]
__device__ __half g_woutT[D_MODEL * D_INNER];        // [1024][2048]

// ---------------- cp.async / ldmatrix helpers -------------------------------
__device__ __forceinline__ void cpa16(uint32_t dst, const void* src) {
    asm volatile("cp.async.cg.shared.global [%0], [%1], 16;\n" ::"r"(dst), "l"(src));
}
__device__ __forceinline__ void cpa_commit() {
    asm volatile("cp.async.commit_group;\n");
}
template <int N>
__device__ __forceinline__ void cpa_wait() {
    asm volatile("cp.async.wait_group %0;\n" ::"n"(N));
}
__device__ __forceinline__ void ldsm4(uint32_t& r0, uint32_t& r1, uint32_t& r2,
                                      uint32_t& r3, uint32_t addr) {
    asm volatile("ldmatrix.sync.aligned.m8n8.x4.shared.b16 {%0,%1,%2,%3}, [%4];"
                 : "=r"(r0), "=r"(r1), "=r"(r2), "=r"(r3) : "r"(addr));
}

// ---------------- 0. weight convert + transpose to fp16 --------------------
__global__ void transpose_h(const float* __restrict__ in, __half* __restrict__ out,
                            int K, int N) {
    __shared__ float t[32][33];
    int n0 = blockIdx.x * 32, k0 = blockIdx.y * 32;
    int tx = threadIdx.x, ty = threadIdx.y;       // 32 x 8
    #pragma unroll
    for (int r = 0; r < 4; ++r) {
        int n = n0 + tx;
        t[ty + r * 8][tx] = (n < N) ? in[(size_t)(k0 + ty + r * 8) * N + n] : 0.f;
    }
    __syncthreads();
    #pragma unroll
    for (int r = 0; r < 4; ++r)
        out[(size_t)(n0 + ty + r * 8) * K + k0 + tx] = __float2half(t[tx][ty + r * 8]);
}

// ---------------- 1. RMSNorm (writes fp16 A for GEMM1) ----------------------
__global__ void rmsnorm_kernel(const float* __restrict__ x,
                               const float* __restrict__ w) {
    int tok = blockIdx.x;
    const float* xp = x + (size_t)tok * D_MODEL;
    float s = 0.f;
    for (int i = threadIdx.x; i < D_MODEL; i += 256) {
        float v = xp[i];
        s += v * v;
    }
    __shared__ float red[8];
    #pragma unroll
    for (int o = 16; o > 0; o >>= 1) s += __shfl_down_sync(0xffffffffu, s, o);
    if ((threadIdx.x & 31) == 0) red[threadIdx.x >> 5] = s;
    __syncthreads();
    if (threadIdx.x < 8) {
        float v = red[threadIdx.x];
        #pragma unroll
        for (int o = 4; o > 0; o >>= 1) v += __shfl_down_sync(0xffu, v, o, 8);
        if (threadIdx.x == 0) red[0] = rsqrtf(v / (float)D_MODEL + 1e-5f);
    }
    __syncthreads();
    float rs = red[0];
    __half* op = g_xn_h + (size_t)tok * D_MODEL;
    for (int i = threadIdx.x; i < D_MODEL; i += 256)
        op[i] = __float2half(xp[i] * rs * w[i]);
}

// ---------------- 2. fp16 tensor-core GEMM (m16n8k16 + ldmatrix) ------------
// C[M,N] = epi(A[M,K](lda,fp16) @ Wt[N][K](fp16)) (+resid)
// BM=BN=128, BK=32, 2-stage cp.async. 8 warps (2x4), warp 64x32.
#define HA 40   // half stride per smem row (80B; conflict-free for ldmatrix)

template <bool NGUARD, int EPI, bool WH>
__global__ __launch_bounds__(256, 2)
void gemm_h16(const __half* __restrict__ A, const __half* __restrict__ Wt,
              const float* __restrict__ resid, const float* __restrict__ bias,
              float* __restrict__ C, __half* __restrict__ Ch,
              int M, int N, int K, int lda) {
    __shared__ __align__(16) __half As[2][128][HA];
    __shared__ __align__(16) __half Bs[2][128][HA];
    int tid = threadIdx.x;
    int lane = tid & 31, warp = tid >> 5;
    int wm = warp & 1, wn = warp >> 1;
    int bm = blockIdx.y * 128, bn = blockIdx.x * 128;
    int t4 = lane >> 2, tm = lane & 3;
    float acc[4][4][4];
    #pragma unroll
    for (int i = 0; i < 4; i++)
        #pragma unroll
        for (int j = 0; j < 4; j++)
            #pragma unroll
            for (int r = 0; r < 4; r++) acc[i][j][r] = 0.f;

    // ldmatrix per-lane address components
    int lr = lane & 7, lg = lane >> 3;
    int aro = (lg & 1) * 8 + lr, aco = (lg >> 1) * 8;   // A: row/col offsets
    int bro = (lg >> 1) * 8 + lr, bco = (lg & 1) * 8;   // B: row/col offsets
    uint32_t smemA = (uint32_t)__cvta_generic_to_shared(&As[0][0][0]);
    uint32_t smemB = (uint32_t)__cvta_generic_to_shared(&Bs[0][0][0]);

    int nt = K >> 5;

    auto issue = [&](int c, int buf) {
        int k0 = c << 5;
        #pragma unroll
        for (int i = 0; i < 2; ++i) {
            int id = tid + i * 256;
            int row = id >> 2, cc = (id & 3) << 3;
            cpa16((uint32_t)__cvta_generic_to_shared(&As[buf][row][cc]),
                  A + (size_t)(bm + row) * lda + k0 + cc);
            cpa16((uint32_t)__cvta_generic_to_shared(&Bs[buf][row][cc]),
                  Wt + (size_t)(bn + row) * K + k0 + cc);
        }
        cpa_commit();
    };

    issue(0, 0);

    for (int c = 0; c < nt; ++c) {
        int buf = c & 1;
        cpa_wait<0>();
        __syncthreads();
        if (c + 1 < nt) issue(c + 1, buf ^ 1);

        #pragma unroll
        for (int ks = 0; ks < 2; ++ks) {
            int kb = ks * 16;
            uint32_t af[4][4], bf[4][2];
            #pragma unroll
            for (int im = 0; im < 4; im++) {
                uint32_t addr = smemA +
                    2u * (((buf << 7) + wm * 64 + im * 16 + aro) * HA + kb + aco);
                ldsm4(af[im][0], af[im][1], af[im][2], af[im][3], addr);
            }
            #pragma unroll
            for (int j2 = 0; j2 < 2; j2++) {
                uint32_t addr = smemB +
                    2u * (((buf << 7) + wn * 32 + j2 * 16 + bro) * HA + kb + bco);
                ldsm4(bf[2 * j2][0], bf[2 * j2][1],
                      bf[2 * j2 + 1][0], bf[2 * j2 + 1][1], addr);
            }
            #pragma unroll
            for (int im = 0; im < 4; im++)
                #pragma unroll
                for (int jn = 0; jn < 4; jn++)
                    asm volatile(
                        "mma.sync.aligned.m16n8k16.row.col.f32.f16.f16.f32 "
                        "{%0,%1,%2,%3}, {%4,%5,%6,%7}, {%8,%9}, {%0,%1,%2,%3};\n"
                        : "+f"(acc[im][jn][0]), "+f"(acc[im][jn][1]),
                          "+f"(acc[im][jn][2]), "+f"(acc[im][jn][3])
                        : "r"(af[im][0]), "r"(af[im][1]),
                          "r"(af[im][2]), "r"(af[im][3]),
                          "r"(bf[jn][0]), "r"(bf[jn][1]));
        }
    }

    int half_n = N >> 1;
    #pragma unroll
    for (int im = 0; im < 4; im++) {
        int row = bm + wm * 64 + im * 16 + t4;
        #pragma unroll
        for (int jn = 0; jn < 4; jn++) {
            int col = bn + wn * 32 + jn * 8 + 2 * tm;
            if (NGUARD && col >= N) continue;
            size_t o0 = (size_t)row * N + col;
            size_t o1 = (size_t)(row + 8) * N + col;
            float v[4] = {acc[im][jn][0], acc[im][jn][1],
                          acc[im][jn][2], acc[im][jn][3]};
            if (EPI == 2) {
                float b0 = bias[col], b1 = bias[col + 1];
                v[0] += b0; v[1] += b1; v[2] += b0; v[3] += b1;
                #pragma unroll
                for (int e = 0; e < 4; e++)
                    v[e] = (v[e] > 20.f) ? v[e] : log1pf(__expf(v[e]));
            } else if (EPI == 1) {
                if (col >= half_n) {
                    #pragma unroll
                    for (int e = 0; e < 4; e++)
                        v[e] = v[e] / (1.f + __expf(-v[e]));
                }
            }
            float2 v0 = make_float2(v[0], v[1]);
            float2 v1 = make_float2(v[2], v[3]);
            if (resid) {
                float2 r0 = *(const float2*)(resid + o0);
                float2 r1 = *(const float2*)(resid + o1);
                v0.x += r0.x; v0.y += r0.y;
                v1.x += r1.x; v1.y += r1.y;
            }
            *(float2*)(C + o0) = v0;
            *(float2*)(C + o1) = v1;
            if (WH) {
                *(__half2*)(Ch + o0) = __floats2half2_rn(v0.x, v0.y);
                *(__half2*)(Ch + o1) = __floats2half2_rn(v1.x, v1.y);
            }
        }
    }
}

// ---------------- 3. depthwise causal conv + bias + SiLU --------------------
__global__ void conv_silu_kernel(const float* __restrict__ cw,
                                 const float* __restrict__ cb) {
    int idx = blockIdx.x * blockDim.x + threadIdx.x;
    if (idx >= NTOK * D_INNER) return;
    int d = idx & (D_INNER - 1);
    int tok = idx >> 11;
    int t = tok & (T_SZ - 1);
    float acc = cb[d];
    #pragma unroll
    for (int k = 0; k < D_CONV; ++k) {
        int tt = t - (D_CONV - 1) + k;
        if (tt >= 0)
            acc = fmaf(g_xr[(size_t)(tok - (D_CONV - 1) + k) * (2 * D_INNER) + d],
                       cw[d * D_CONV + k], acc);
    }
    float u = acc / (1.f + __expf(-acc));
    g_u[idx] = u;
    g_u_h[idx] = __float2half(u);
}

// ---------------- 6. smem-staged selective scan (res pre-silued) ------------
#define SCAN_TC 32
#define SCAN_CH 32
#define SCAN_NC (T_SZ / SCAN_TC)

__global__ __launch_bounds__(512, 1)
void scan_kernel(const float* __restrict__ A_log, const float* __restrict__ Dp) {
    __shared__ float sD[2][SCAN_TC][SCAN_CH];
    __shared__ float sU[2][SCAN_TC][SCAN_CH];
    __shared__ float sR[2][SCAN_TC][SCAN_CH];
    __shared__ float sBC[2][SCAN_TC][32];
    __shared__ float sY[SCAN_TC][SCAN_CH];

    int tid = threadIdx.x;
    int bb = blockIdx.x >> 6;
    int d0 = (blockIdx.x & 63) * SCAN_CH;
    size_t tokbase = (size_t)bb * T_SZ;

    int lidx = tid & 255;
    int li = lidx >> 3;
    int lj = (lidx & 7) << 2;
    int lgrp = tid >> 8;

    int warp = tid >> 5, lane = tid & 31;
    int ch = warp * 2 + (lane >> 4);
    int n = lane & 15;
    int dg = d0 + ch;
    float a = -__expf(A_log[dg * D_STATE + n]);
    float Dv = Dp[dg];
    float h = 0.f;

    auto issue_chunk = [&](int c, int buf) {
        size_t tok = tokbase + (size_t)c * SCAN_TC + li;
        if (lgrp == 0) {
            cpa16((uint32_t)__cvta_generic_to_shared(&sD[buf][li][lj]),
                  g_delta + tok * D_INNER + d0 + lj);
            cpa16((uint32_t)__cvta_generic_to_shared(&sU[buf][li][lj]),
                  g_u + tok * D_INNER + d0 + lj);
        } else {
            cpa16((uint32_t)__cvta_generic_to_shared(&sR[buf][li][lj]),
                  g_xr + tok * (2 * D_INNER) + D_INNER + d0 + lj);
            cpa16((uint32_t)__cvta_generic_to_shared(&sBC[buf][li][lj]),
                  g_xdbc + tok * XDBC_W + DT_RANK + lj);
        }
        cpa_commit();
    };

    issue_chunk(0, 0);

    for (int c = 0; c < SCAN_NC; ++c) {
        int buf = c & 1;
        if (c + 1 < SCAN_NC) {
            issue_chunk(c + 1, buf ^ 1);
            cpa_wait<1>();
        } else {
            cpa_wait<0>();
        }
        __syncthreads();

        #pragma unroll 4
        for (int t = 0; t < SCAN_TC; ++t) {
            float dv = sD[buf][t][ch];
            float uv = sU[buf][t][ch];
            float Bv = sBC[buf][t][n];
            float Cv = sBC[buf][t][16 + n];
            h = fmaf(__expf(dv * a), h, (dv * uv) * Bv);
            float p = h * Cv;
            p += __shfl_down_sync(0xffffffffu, p, 8, 16);
            p += __shfl_down_sync(0xffffffffu, p, 4, 16);
            p += __shfl_down_sync(0xffffffffu, p, 2, 16);
            p += __shfl_down_sync(0xffffffffu, p, 1, 16);
            if (n == 0) {
                sY[t][ch] = fmaf(uv, Dv, p) * sR[buf][t][ch];
            }
        }
        __syncthreads();

        if (lgrp == 0) {
            size_t tok = tokbase + (size_t)c * SCAN_TC + li;
            float4 v = *(float4*)(&sY[li][lj]);
            __half* dst = g_y_h + tok * D_INNER + d0 + lj;
            *(__half2*)(dst) = __floats2half2_rn(v.x, v.y);
            *(__half2*)(dst + 2) = __floats2half2_rn(v.z, v.w);
        }
    }
}

// ---------------- launch ----------------------------------------------------
extern "C" void kernel_launch(void* const* d_in, const int* in_sizes, int n_in,
                              void* d_out, int out_size) {
    const float* x      = (const float*)d_in[0];
    const float* norm_w = (const float*)d_in[1];
    const float* w_in   = (const float*)d_in[2];
    const float* conv_w = (const float*)d_in[3];
    const float* conv_b = (const float*)d_in[4];
    const float* w_x    = (const float*)d_in[5];
    const float* w_dt   = (const float*)d_in[6];
    const float* b_dt   = (const float*)d_in[7];
    const float* A_log  = (const float*)d_in[8];
    const float* Dp     = (const float*)d_in[9];
    const float* w_out  = (const float*)d_in[10];
    float* out = (float*)d_out;

    void *p_xn_h, *p_xr, *p_u_h, *p_xdbc, *p_xdbc_h, *p_delta, *p_y_h;
    void *p_winT, *p_wxT, *p_wdtT, *p_woutT;
    cudaGetSymbolAddress(&p_xn_h, g_xn_h);
    cudaGetSymbolAddress(&p_xr, g_xr);
    cudaGetSymbolAddress(&p_u_h, g_u_h);
    cudaGetSymbolAddress(&p_xdbc, g_xdbc);
    cudaGetSymbolAddress(&p_xdbc_h, g_xdbc_h);
    cudaGetSymbolAddress(&p_delta, g_delta);
    cudaGetSymbolAddress(&p_y_h, g_y_h);
    cudaGetSymbolAddress(&p_winT, g_winT);
    cudaGetSymbolAddress(&p_wxT, g_wxT);
    cudaGetSymbolAddress(&p_wdtT, g_wdtT);
    cudaGetSymbolAddress(&p_woutT, g_woutT);

    dim3 tb(32, 8);
    transpose_h<<<dim3(2 * D_INNER / 32, D_MODEL / 32), tb>>>(
        w_in, (__half*)p_winT, D_MODEL, 2 * D_INNER);
    transpose_h<<<dim3(128 / 32, D_INNER / 32), tb>>>(
        w_x, (__half*)p_wxT, D_INNER, XDBC_W);
    transpose_h<<<dim3(D_INNER / 32, DT_RANK / 32), tb>>>(
        w_dt, (__half*)p_wdtT, DT_RANK, D_INNER);
    transpose_h<<<dim3(D_MODEL / 32, D_INNER / 32), tb>>>(
        w_out, (__half*)p_woutT, D_INNER, D_MODEL);

    rmsnorm_kernel<<<NTOK, 256>>>(x, norm_w);

    // xr = xn @ w_in ; silu on res half
    gemm_h16<false, 1, false><<<dim3(2 * D_INNER / 128, NTOK / 128), 256>>>(
        (const __half*)p_xn_h, (const __half*)p_winT, nullptr, nullptr,
        (float*)p_xr, nullptr, NTOK, 2 * D_INNER, D_MODEL, D_MODEL);

    conv_silu_kernel<<<(NTOK * D_INNER + 255) / 256, 256>>>(conv_w, conv_b);

    // xdbc = u @ w_x  (N=96, store fp32 + fp16)
    gemm_h16<true, 0, true><<<dim3(1, NTOK / 128), 256>>>(
        (const __half*)p_u_h, (const __half*)p_wxT, nullptr, nullptr,
        (float*)p_xdbc, (__half*)p_xdbc_h, NTOK, XDBC_W, D_INNER, D_INNER);

    // delta = softplus(dt @ w_dt + b_dt)  (K=64, A lda=96)
    gemm_h16<false, 2, false><<<dim3(D_INNER / 128, NTOK / 128), 256>>>(
        (const __half*)p_xdbc_h, (const __half*)p_wdtT, nullptr, b_dt,
        (float*)p_delta, nullptr, NTOK, D_INNER, DT_RANK, XDBC_W);

    scan_kernel<<<B_SZ * D_INNER / SCAN_CH, 512>>>(A_log, Dp);

    // out = y @ w_out + x
    gemm_h16<false, 0, false><<<dim3(D_MODEL / 128, NTOK / 128), 256>>>(
        (const __half*)p_y_h, (const __half*)p_woutT, x, nullptr,
        out, nullptr, NTOK, D_MODEL, D_INNER, D_INNER);
}

// round 12
// speedup vs baseline: 1.2497x; 1.0110x over previous
#include <cuda_runtime.h>
#include <cuda_fp16.h>
#include <cstdint>

#define B_SZ 2
#define T_SZ 4096
#define D_MODEL 1024
#define D_STATE 16
#define D_CONV 4
#define D_INNER 2048
#define DT_RANK 64
#define NTOK (B_SZ * T_SZ)              // 8192
#define XDBC_W (DT_RANK + 2 * D_STATE)  // 96

// ---------------- scratch (device globals; no allocation allowed) ----------
__device__ __half g_xn_h[NTOK * D_MODEL];
__device__ __half g_xr_h[NTOK * 2 * D_INNER];    // [u_pre | silu(res)] fp16
__device__ __half g_u_h[NTOK * D_INNER];
__device__ float  g_xdbc[NTOK * XDBC_W];
__device__ __half g_xdbc_h[NTOK * XDBC_W];
__device__ float  g_delta[NTOK * D_INNER];       // fp32 (scan precision)
__device__ __half g_y_h[NTOK * D_INNER];
// transposed fp16 weights  Wt[n][k]
__device__ __half g_winT[2 * D_INNER * D_MODEL];
__device__ __half g_wxT[128 * D_INNER];
__device__ __half g_wdtT[D_INNER * DT_RANK];
__device__ __half g_woutT[D_MODEL * D_INNER];

// ---------------- cp.async / ldmatrix helpers -------------------------------
__device__ __forceinline__ void cpa16(uint32_t dst, const void* src) {
    asm volatile("cp.async.cg.shared.global [%0], [%1], 16;\n" ::"r"(dst), "l"(src));
}
__device__ __forceinline__ void cpa_commit() {
    asm volatile("cp.async.commit_group;\n");
}
template <int N>
__device__ __forceinline__ void cpa_wait() {
    asm volatile("cp.async.wait_group %0;\n" ::"n"(N));
}
__device__ __forceinline__ void ldsm4(uint32_t& r0, uint32_t& r1, uint32_t& r2,
                                      uint32_t& r3, uint32_t addr) {
    asm volatile("ldmatrix.sync.aligned.m8n8.x4.shared.b16 {%0,%1,%2,%3}, [%4];"
                 : "=r"(r0), "=r"(r1), "=r"(r2), "=r"(r3) : "r"(addr));
}

// ---------------- 0. weight convert + transpose to fp16 --------------------
__global__ void transpose_h(const float* __restrict__ in, __half* __restrict__ out,
                            int K, int N) {
    __shared__ float t[32][33];
    int n0 = blockIdx.x * 32, k0 = blockIdx.y * 32;
    int tx = threadIdx.x, ty = threadIdx.y;       // 32 x 8
    #pragma unroll
    for (int r = 0; r < 4; ++r) {
        int n = n0 + tx;
        t[ty + r * 8][tx] = (n < N) ? in[(size_t)(k0 + ty + r * 8) * N + n] : 0.f;
    }
    __syncthreads();
    #pragma unroll
    for (int r = 0; r < 4; ++r)
        out[(size_t)(n0 + ty + r * 8) * K + k0 + tx] = __float2half(t[tx][ty + r * 8]);
}

// ---------------- 1. RMSNorm (writes fp16 A for GEMM1) ----------------------
__global__ void rmsnorm_kernel(const float* __restrict__ x,
                               const float* __restrict__ w) {
    int tok = blockIdx.x;
    const float* xp = x + (size_t)tok * D_MODEL;
    float s = 0.f;
    for (int i = threadIdx.x; i < D_MODEL; i += 256) {
        float v = xp[i];
        s += v * v;
    }
    __shared__ float red[8];
    #pragma unroll
    for (int o = 16; o > 0; o >>= 1) s += __shfl_down_sync(0xffffffffu, s, o);
    if ((threadIdx.x & 31) == 0) red[threadIdx.x >> 5] = s;
    __syncthreads();
    if (threadIdx.x < 8) {
        float v = red[threadIdx.x];
        #pragma unroll
        for (int o = 4; o > 0; o >>= 1) v += __shfl_down_sync(0xffu, v, o, 8);
        if (threadIdx.x == 0) red[0] = rsqrtf(v / (float)D_MODEL + 1e-5f);
    }
    __syncthreads();
    float rs = red[0];
    __half* op = g_xn_h + (size_t)tok * D_MODEL;
    for (int i = threadIdx.x; i < D_MODEL; i += 256)
        op[i] = __float2half(xp[i] * rs * w[i]);
}

// ---------------- 2. fp16 tensor-core GEMM (m16n8k16 + ldmatrix) ------------
// C = epi(A[M,K](lda) @ Wt[N][K]) (+resid). BM=BN=128, BK=32.
// 2-stage cp.async, issue-before-wait (full overlap). 8 warps (2x4), warp 64x32.
// EPI: 0 none, 1 silu col>=N/2, 2 softplus+bias.
// OUT: 0 fp32 only, 1 fp16 only, 2 both.
#define HA 40   // half stride per smem row (80B; conflict-free for ldmatrix)

template <bool NGUARD, int EPI, int OUT>
__global__ __launch_bounds__(256, 2)
void gemm_h16(const __half* __restrict__ A, const __half* __restrict__ Wt,
              const float* __restrict__ resid, const float* __restrict__ bias,
              float* __restrict__ C, __half* __restrict__ Ch,
              int M, int N, int K, int lda) {
    __shared__ __align__(16) __half As[2][128][HA];
    __shared__ __align__(16) __half Bs[2][128][HA];
    int tid = threadIdx.x;
    int lane = tid & 31, warp = tid >> 5;
    int wm = warp & 1, wn = warp >> 1;
    int bm = blockIdx.y * 128, bn = blockIdx.x * 128;
    int t4 = lane >> 2, tm = lane & 3;
    float acc[4][4][4];
    #pragma unroll
    for (int i = 0; i < 4; i++)
        #pragma unroll
        for (int j = 0; j < 4; j++)
            #pragma unroll
            for (int r = 0; r < 4; r++) acc[i][j][r] = 0.f;

    int lr = lane & 7, lg = lane >> 3;
    int aro = (lg & 1) * 8 + lr, aco = (lg >> 1) * 8;
    int bro = (lg >> 1) * 8 + lr, bco = (lg & 1) * 8;
    uint32_t smemA = (uint32_t)__cvta_generic_to_shared(&As[0][0][0]);
    uint32_t smemB = (uint32_t)__cvta_generic_to_shared(&Bs[0][0][0]);

    int nt = K >> 5;

    auto issue = [&](int c, int buf) {
        int k0 = c << 5;
        #pragma unroll
        for (int i = 0; i < 2; ++i) {
            int id = tid + i * 256;
            int row = id >> 2, cc = (id & 3) << 3;
            cpa16((uint32_t)__cvta_generic_to_shared(&As[buf][row][cc]),
                  A + (size_t)(bm + row) * lda + k0 + cc);
            cpa16((uint32_t)__cvta_generic_to_shared(&Bs[buf][row][cc]),
                  Wt + (size_t)(bn + row) * K + k0 + cc);
        }
        cpa_commit();
    };

    issue(0, 0);

    for (int c = 0; c < nt; ++c) {
        int buf = c & 1;
        if (c + 1 < nt) {
            issue(c + 1, buf ^ 1);   // keep one full stage in flight
            cpa_wait<1>();
        } else {
            cpa_wait<0>();
        }
        __syncthreads();

        #pragma unroll
        for (int ks = 0; ks < 2; ++ks) {
            int kb = ks * 16;
            uint32_t af[4][4], bf[4][2];
            #pragma unroll
            for (int im = 0; im < 4; im++) {
                uint32_t addr = smemA +
                    2u * (((buf << 7) + wm * 64 + im * 16 + aro) * HA + kb + aco);
                ldsm4(af[im][0], af[im][1], af[im][2], af[im][3], addr);
            }
            #pragma unroll
            for (int j2 = 0; j2 < 2; j2++) {
                uint32_t addr = smemB +
                    2u * (((buf << 7) + wn * 32 + j2 * 16 + bro) * HA + kb + bco);
                ldsm4(bf[2 * j2][0], bf[2 * j2][1],
                      bf[2 * j2 + 1][0], bf[2 * j2 + 1][1], addr);
            }
            #pragma unroll
            for (int im = 0; im < 4; im++)
                #pragma unroll
                for (int jn = 0; jn < 4; jn++)
                    asm volatile(
                        "mma.sync.aligned.m16n8k16.row.col.f32.f16.f16.f32 "
                        "{%0,%1,%2,%3}, {%4,%5,%6,%7}, {%8,%9}, {%0,%1,%2,%3};\n"
                        : "+f"(acc[im][jn][0]), "+f"(acc[im][jn][1]),
                          "+f"(acc[im][jn][2]), "+f"(acc[im][jn][3])
                        : "r"(af[im][0]), "r"(af[im][1]),
                          "r"(af[im][2]), "r"(af[im][3]),
                          "r"(bf[jn][0]), "r"(bf[jn][1]));
        }
        __syncthreads();   // retire compute before issue overwrites this buf
    }

    int half_n = N >> 1;
    #pragma unroll
    for (int im = 0; im < 4; im++) {
        int row = bm + wm * 64 + im * 16 + t4;
        #pragma unroll
        for (int jn = 0; jn < 4; jn++) {
            int col = bn + wn * 32 + jn * 8 + 2 * tm;
            if (NGUARD && col >= N) continue;
            size_t o0 = (size_t)row * N + col;
            size_t o1 = (size_t)(row + 8) * N + col;
            float v[4] = {acc[im][jn][0], acc[im][jn][1],
                          acc[im][jn][2], acc[im][jn][3]};
            if (EPI == 2) {
                float b0 = bias[col], b1 = bias[col + 1];
                v[0] += b0; v[1] += b1; v[2] += b0; v[3] += b1;
                #pragma unroll
                for (int e = 0; e < 4; e++)
                    v[e] = (v[e] > 20.f) ? v[e] : log1pf(__expf(v[e]));
            } else if (EPI == 1) {
                if (col >= half_n) {
                    #pragma unroll
                    for (int e = 0; e < 4; e++)
                        v[e] = v[e] / (1.f + __expf(-v[e]));
                }
            }
            if (resid) {
                float2 r0 = *(const float2*)(resid + o0);
                float2 r1 = *(const float2*)(resid + o1);
                v[0] += r0.x; v[1] += r0.y;
                v[2] += r1.x; v[3] += r1.y;
            }
            if (OUT == 0 || OUT == 2) {
                *(float2*)(C + o0) = make_float2(v[0], v[1]);
                *(float2*)(C + o1) = make_float2(v[2], v[3]);
            }
            if (OUT == 1 || OUT == 2) {
                *(__half2*)(Ch + o0) = __floats2half2_rn(v[0], v[1]);
                *(__half2*)(Ch + o1) = __floats2half2_rn(v[2], v[3]);
            }
        }
    }
}

// ---------------- 3. depthwise causal conv + bias + SiLU (half2) ------------
__global__ void conv_silu_kernel(const float* __restrict__ cw,
                                 const float* __restrict__ cb) {
    int idx = blockIdx.x * blockDim.x + threadIdx.x;   // over NTOK * 1024 pairs
    if (idx >= NTOK * (D_INNER / 2)) return;
    int dp = idx & (D_INNER / 2 - 1);
    int d = dp * 2;
    int tok = idx >> 10;
    int t = tok & (T_SZ - 1);
    float a0 = cb[d], a1 = cb[d + 1];
    #pragma unroll
    for (int k = 0; k < D_CONV; ++k) {
        int tt = t - (D_CONV - 1) + k;
        if (tt >= 0) {
            __half2 v = *(const __half2*)(g_xr_h +
                (size_t)(tok - (D_CONV - 1) + k) * (2 * D_INNER) + d);
            float2 vf = __half22float2(v);
            a0 = fmaf(vf.x, cw[d * D_CONV + k], a0);
            a1 = fmaf(vf.y, cw[(d + 1) * D_CONV + k], a1);
        }
    }
    a0 = a0 / (1.f + __expf(-a0));
    a1 = a1 / (1.f + __expf(-a1));
    *(__half2*)(g_u_h + (size_t)tok * D_INNER + d) = __floats2half2_rn(a0, a1);
}

// ---------------- 6. smem-staged selective scan ------------------------------
// inputs: delta fp32, u fp16, res fp16, B/C fp32
#define SCAN_TC 32
#define SCAN_CH 32
#define SCAN_NC (T_SZ / SCAN_TC)

__global__ __launch_bounds__(512, 1)
void scan_kernel(const float* __restrict__ A_log, const float* __restrict__ Dp) {
    __shared__ float  sD[2][SCAN_TC][SCAN_CH];
    __shared__ __half sU[2][SCAN_TC][SCAN_CH];
    __shared__ __half sR[2][SCAN_TC][SCAN_CH];
    __shared__ float  sBC[2][SCAN_TC][32];
    __shared__ float  sY[SCAN_TC][SCAN_CH];

    int tid = threadIdx.x;
    int bb = blockIdx.x >> 6;
    int d0 = (blockIdx.x & 63) * SCAN_CH;
    size_t tokbase = (size_t)bb * T_SZ;

    // y-store mapping (256 threads)
    int li = (tid & 255) >> 3;
    int lj = ((tid & 255) & 7) << 2;

    int warp = tid >> 5, lane = tid & 31;
    int ch = warp * 2 + (lane >> 4);
    int n = lane & 15;
    int dg = d0 + ch;
    float a = -__expf(A_log[dg * D_STATE + n]);
    float Dv = Dp[dg];
    float h = 0.f;

    auto issue_chunk = [&](int c, int buf) {
        size_t t0 = tokbase + (size_t)c * SCAN_TC;
        if (tid < 256) {
            // sD: 256 chunks of 4 floats
            int r = tid >> 3, c4 = (tid & 7) << 2;
            cpa16((uint32_t)__cvta_generic_to_shared(&sD[buf][r][c4]),
                  g_delta + (t0 + r) * D_INNER + d0 + c4);
            if (tid < 128) {   // sU: 128 chunks of 8 halves
                int r2 = tid >> 2, c8 = (tid & 3) << 3;
                cpa16((uint32_t)__cvta_generic_to_shared(&sU[buf][r2][c8]),
                      g_u_h + (t0 + r2) * D_INNER + d0 + c8);
            } else {           // sR: 128 chunks of 8 halves
                int id = tid - 128;
                int r2 = id >> 2, c8 = (id & 3) << 3;
                cpa16((uint32_t)__cvta_generic_to_shared(&sR[buf][r2][c8]),
                      g_xr_h + (t0 + r2) * (2 * D_INNER) + D_INNER + d0 + c8);
            }
        } else {
            // sBC: 256 chunks of 4 floats
            int id = tid - 256;
            int r = id >> 3, c4 = (id & 7) << 2;
            cpa16((uint32_t)__cvta_generic_to_shared(&sBC[buf][r][c4]),
                  g_xdbc + (t0 + r) * XDBC_W + DT_RANK + c4);
        }
        cpa_commit();
    };

    issue_chunk(0, 0);

    for (int c = 0; c < SCAN_NC; ++c) {
        int buf = c & 1;
        if (c + 1 < SCAN_NC) {
            issue_chunk(c + 1, buf ^ 1);
            cpa_wait<1>();
        } else {
            cpa_wait<0>();
        }
        __syncthreads();

        #pragma unroll 4
        for (int t = 0; t < SCAN_TC; ++t) {
            float dv = sD[buf][t][ch];
            float uv = __half2float(sU[buf][t][ch]);
            float Bv = sBC[buf][t][n];
            float Cv = sBC[buf][t][16 + n];
            h = fmaf(__expf(dv * a), h, (dv * uv) * Bv);
            float p = h * Cv;
            p += __shfl_down_sync(0xffffffffu, p, 8, 16);
            p += __shfl_down_sync(0xffffffffu, p, 4, 16);
            p += __shfl_down_sync(0xffffffffu, p, 2, 16);
            p += __shfl_down_sync(0xffffffffu, p, 1, 16);
            if (n == 0) {
                sY[t][ch] = fmaf(uv, Dv, p) * __half2float(sR[buf][t][ch]);
            }
        }
        __syncthreads();

        if (tid < 256) {
            size_t tok = tokbase + (size_t)c * SCAN_TC + li;
            float4 v = *(float4*)(&sY[li][lj]);
            __half* dst = g_y_h + tok * D_INNER + d0 + lj;
            *(__half2*)(dst) = __floats2half2_rn(v.x, v.y);
            *(__half2*)(dst + 2) = __floats2half2_rn(v.z, v.w);
        }
    }
}

// ---------------- launch ----------------------------------------------------
extern "C" void kernel_launch(void* const* d_in, const int* in_sizes, int n_in,
                              void* d_out, int out_size) {
    const float* x      = (const float*)d_in[0];
    const float* norm_w = (const float*)d_in[1];
    const float* w_in   = (const float*)d_in[2];
    const float* conv_w = (const float*)d_in[3];
    const float* conv_b = (const float*)d_in[4];
    const float* w_x    = (const float*)d_in[5];
    const float* w_dt   = (const float*)d_in[6];
    const float* b_dt   = (const float*)d_in[7];
    const float* A_log  = (const float*)d_in[8];
    const float* Dp     = (const float*)d_in[9];
    const float* w_out  = (const float*)d_in[10];
    float* out = (float*)d_out;

    void *p_xn_h, *p_xr_h, *p_u_h, *p_xdbc, *p_xdbc_h, *p_delta, *p_y_h;
    void *p_winT, *p_wxT, *p_wdtT, *p_woutT;
    cudaGetSymbolAddress(&p_xn_h, g_xn_h);
    cudaGetSymbolAddress(&p_xr_h, g_xr_h);
    cudaGetSymbolAddress(&p_u_h, g_u_h);
    cudaGetSymbolAddress(&p_xdbc, g_xdbc);
    cudaGetSymbolAddress(&p_xdbc_h, g_xdbc_h);
    cudaGetSymbolAddress(&p_delta, g_delta);
    cudaGetSymbolAddress(&p_y_h, g_y_h);
    cudaGetSymbolAddress(&p_winT, g_winT);
    cudaGetSymbolAddress(&p_wxT, g_wxT);
    cudaGetSymbolAddress(&p_wdtT, g_wdtT);
    cudaGetSymbolAddress(&p_woutT, g_woutT);

    dim3 tb(32, 8);
    transpose_h<<<dim3(2 * D_INNER / 32, D_MODEL / 32), tb>>>(
        w_in, (__half*)p_winT, D_MODEL, 2 * D_INNER);
    transpose_h<<<dim3(128 / 32, D_INNER / 32), tb>>>(
        w_x, (__half*)p_wxT, D_INNER, XDBC_W);
    transpose_h<<<dim3(D_INNER / 32, DT_RANK / 32), tb>>>(
        w_dt, (__half*)p_wdtT, DT_RANK, D_INNER);
    transpose_h<<<dim3(D_MODEL / 32, D_INNER / 32), tb>>>(
        w_out, (__half*)p_woutT, D_INNER, D_MODEL);

    rmsnorm_kernel<<<NTOK, 256>>>(x, norm_w);

    // xr_h = [xn @ w_in] with silu on res half — fp16 out only
    gemm_h16<false, 1, 1><<<dim3(2 * D_INNER / 128, NTOK / 128), 256>>>(
        (const __half*)p_xn_h, (const __half*)p_winT, nullptr, nullptr,
        nullptr, (__half*)p_xr_h, NTOK, 2 * D_INNER, D_MODEL, D_MODEL);

    conv_silu_kernel<<<(NTOK * D_INNER / 2 + 255) / 256, 256>>>(conv_w, conv_b);

    // xdbc = u @ w_x  (N=96; fp32 for scan B/C + fp16 for delta GEMM)
    gemm_h16<true, 0, 2><<<dim3(1, NTOK / 128), 256>>>(
        (const __half*)p_u_h, (const __half*)p_wxT, nullptr, nullptr,
        (float*)p_xdbc, (__half*)p_xdbc_h, NTOK, XDBC_W, D_INNER, D_INNER);

    // delta = softplus(dt @ w_dt + b_dt)  (K=64, A lda=96) — fp32 out
    gemm_h16<false, 2, 0><<<dim3(D_INNER / 128, NTOK / 128), 256>>>(
        (const __half*)p_xdbc_h, (const __half*)p_wdtT, nullptr, b_dt,
        (float*)p_delta, nullptr, NTOK, D_INNER, DT_RANK, XDBC_W);

    scan_kernel<<<B_SZ * D_INNER / SCAN_CH, 512>>>(A_log, Dp);

    // out = y @ w_out + x  — fp32 out
    gemm_h16<false, 0, 0><<<dim3(D_MODEL / 128, NTOK / 128), 256>>>(
        (const __half*)p_y_h, (const __half*)p_woutT, x, nullptr,
        out, nullptr, NTOK, D_MODEL, D_INNER, D_INNER);
}

// round 15
// speedup vs baseline: 1.2751x; 1.0203x over previous
#include <cuda_runtime.h>
#include <cuda_fp16.h>
#include <cstdint>

#define B_SZ 2
#define T_SZ 4096
#define D_MODEL 1024
#define D_STATE 16
#define D_CONV 4
#define D_INNER 2048
#define DT_RANK 64
#define NTOK (B_SZ * T_SZ)              // 8192
#define XDBC_W (DT_RANK + 2 * D_STATE)  // 96

// ---------------- scratch (device globals; no allocation allowed) ----------
__device__ __half g_xn_h[NTOK * D_MODEL];
__device__ __half g_xr_h[NTOK * 2 * D_INNER];    // [u_pre | silu(res)] fp16
__device__ __half g_u_h[NTOK * D_INNER];
__device__ float  g_xdbc[NTOK * XDBC_W];
__device__ __half g_xdbc_h[NTOK * XDBC_W];
__device__ float  g_delta[NTOK * D_INNER];       // fp32 (scan precision)
__device__ __half g_y_h[NTOK * D_INNER];
// transposed fp16 weights  Wt[n][k]
__device__ __half g_winT[2 * D_INNER * D_MODEL];
__device__ __half g_wxT[128 * D_INNER];
__device__ __half g_wdtT[D_INNER * DT_RANK];
__device__ __half g_woutT[D_MODEL * D_INNER];

// ---------------- cp.async / ldmatrix helpers -------------------------------
__device__ __forceinline__ void cpa16(uint32_t dst, const void* src) {
    asm volatile("cp.async.cg.shared.global [%0], [%1], 16;\n" ::"r"(dst), "l"(src));
}
__device__ __forceinline__ void cpa_commit() {
    asm volatile("cp.async.commit_group;\n");
}
template <int N>
__device__ __forceinline__ void cpa_wait() {
    asm volatile("cp.async.wait_group %0;\n" ::"n"(N));
}
__device__ __forceinline__ void ldsm4(uint32_t& r0, uint32_t& r1, uint32_t& r2,
                                      uint32_t& r3, uint32_t addr) {
    asm volatile("ldmatrix.sync.aligned.m8n8.x4.shared.b16 {%0,%1,%2,%3}, [%4];"
                 : "=r"(r0), "=r"(r1), "=r"(r2), "=r"(r3) : "r"(addr));
}

// ---------------- 0. weight convert + transpose to fp16 --------------------
__global__ void transpose_h(const float* __restrict__ in, __half* __restrict__ out,
                            int K, int N) {
    __shared__ float t[32][33];
    int n0 = blockIdx.x * 32, k0 = blockIdx.y * 32;
    int tx = threadIdx.x, ty = threadIdx.y;       // 32 x 8
    #pragma unroll
    for (int r = 0; r < 4; ++r) {
        int n = n0 + tx;
        t[ty + r * 8][tx] = (n < N) ? in[(size_t)(k0 + ty + r * 8) * N + n] : 0.f;
    }
    __syncthreads();
    #pragma unroll
    for (int r = 0; r < 4; ++r)
        out[(size_t)(n0 + ty + r * 8) * K + k0 + tx] = __float2half(t[tx][ty + r * 8]);
}

// ---------------- 1. RMSNorm (writes fp16 A for GEMM1) ----------------------
__global__ void rmsnorm_kernel(const float* __restrict__ x,
                               const float* __restrict__ w) {
    int tok = blockIdx.x;
    const float* xp = x + (size_t)tok * D_MODEL;
    float s = 0.f;
    for (int i = threadIdx.x; i < D_MODEL; i += 256) {
        float v = xp[i];
        s += v * v;
    }
    __shared__ float red[8];
    #pragma unroll
    for (int o = 16; o > 0; o >>= 1) s += __shfl_down_sync(0xffffffffu, s, o);
    if ((threadIdx.x & 31) == 0) red[threadIdx.x >> 5] = s;
    __syncthreads();
    if (threadIdx.x < 8) {
        float v = red[threadIdx.x];
        #pragma unroll
        for (int o = 4; o > 0; o >>= 1) v += __shfl_down_sync(0xffu, v, o, 8);
        if (threadIdx.x == 0) red[0] = rsqrtf(v / (float)D_MODEL + 1e-5f);
    }
    __syncthreads();
    float rs = red[0];
    __half* op = g_xn_h + (size_t)tok * D_MODEL;
    for (int i = threadIdx.x; i < D_MODEL; i += 256)
        op[i] = __float2half(xp[i] * rs * w[i]);
}

// ---------------- 2. fp16 tensor-core GEMM (warp tile 64x64) ----------------
// C = epi(A[M,K](lda) @ Wt[N][K]) (+resid). BM=BN=128, BK=32.
// 128 threads, 4 warps (2x2), warp tile 64x64 = 4x8 m16n8k16 per ks.
// 2-stage cp.async, issue-before-wait. EPI: 0 none, 1 silu col>=N/2,
// 2 softplus+bias. OUT: 0 fp32, 1 fp16, 2 both.
#define HA 40   // half stride per smem row (80B; conflict-free for ldmatrix)

template <bool NGUARD, int EPI, int OUT>
__global__ __launch_bounds__(128, 2)
void gemm_h16(const __half* __restrict__ A, const __half* __restrict__ Wt,
              const float* __restrict__ resid, const float* __restrict__ bias,
              float* __restrict__ C, __half* __restrict__ Ch,
              int M, int N, int K, int lda) {
    __shared__ __align__(16) __half As[2][128][HA];
    __shared__ __align__(16) __half Bs[2][128][HA];
    int tid = threadIdx.x;
    int lane = tid & 31, warp = tid >> 5;        // 4 warps
    int wm = warp & 1, wn = warp >> 1;           // 2 x 2
    int bm = blockIdx.y * 128, bn = blockIdx.x * 128;
    int t4 = lane >> 2, tm = lane & 3;
    float acc[4][8][4];
    #pragma unroll
    for (int i = 0; i < 4; i++)
        #pragma unroll
        for (int j = 0; j < 8; j++)
            #pragma unroll
            for (int r = 0; r < 4; r++) acc[i][j][r] = 0.f;

    int lr = lane & 7, lg = lane >> 3;
    int aro = (lg & 1) * 8 + lr, aco = (lg >> 1) * 8;
    int bro = (lg >> 1) * 8 + lr, bco = (lg & 1) * 8;
    uint32_t smemA = (uint32_t)__cvta_generic_to_shared(&As[0][0][0]);
    uint32_t smemB = (uint32_t)__cvta_generic_to_shared(&Bs[0][0][0]);

    int nt = K >> 5;

    auto issue = [&](int c, int buf) {
        int k0 = c << 5;
        #pragma unroll
        for (int i = 0; i < 4; ++i) {
            int id = tid + i * 128;
            int row = id >> 2, cc = (id & 3) << 3;
            cpa16((uint32_t)__cvta_generic_to_shared(&As[buf][row][cc]),
                  A + (size_t)(bm + row) * lda + k0 + cc);
            cpa16((uint32_t)__cvta_generic_to_shared(&Bs[buf][row][cc]),
                  Wt + (size_t)(bn + row) * K + k0 + cc);
        }
        cpa_commit();
    };

    issue(0, 0);

    for (int c = 0; c < nt; ++c) {
        int buf = c & 1;
        if (c + 1 < nt) {
            issue(c + 1, buf ^ 1);   // keep one full stage in flight
            cpa_wait<1>();
        } else {
            cpa_wait<0>();
        }
        __syncthreads();

        #pragma unroll
        for (int ks = 0; ks < 2; ++ks) {
            int kb = ks * 16;
            uint32_t af[4][4], bf[8][2];
            #pragma unroll
            for (int im = 0; im < 4; im++) {
                uint32_t addr = smemA +
                    2u * (((buf << 7) + wm * 64 + im * 16 + aro) * HA + kb + aco);
                ldsm4(af[im][0], af[im][1], af[im][2], af[im][3], addr);
            }
            #pragma unroll
            for (int j2 = 0; j2 < 4; j2++) {
                uint32_t addr = smemB +
                    2u * (((buf << 7) + wn * 64 + j2 * 16 + bro) * HA + kb + bco);
                ldsm4(bf[2 * j2][0], bf[2 * j2][1],
                      bf[2 * j2 + 1][0], bf[2 * j2 + 1][1], addr);
            }
            #pragma unroll
            for (int im = 0; im < 4; im++)
                #pragma unroll
                for (int jn = 0; jn < 8; jn++)
                    asm volatile(
                        "mma.sync.aligned.m16n8k16.row.col.f32.f16.f16.f32 "
                        "{%0,%1,%2,%3}, {%4,%5,%6,%7}, {%8,%9}, {%0,%1,%2,%3};\n"
                        : "+f"(acc[im][jn][0]), "+f"(acc[im][jn][1]),
                          "+f"(acc[im][jn][2]), "+f"(acc[im][jn][3])
                        : "r"(af[im][0]), "r"(af[im][1]),
                          "r"(af[im][2]), "r"(af[im][3]),
                          "r"(bf[jn][0]), "r"(bf[jn][1]));
        }
        __syncthreads();   // retire compute before issue overwrites this buf
    }

    int half_n = N >> 1;
    #pragma unroll
    for (int im = 0; im < 4; im++) {
        int row = bm + wm * 64 + im * 16 + t4;
        #pragma unroll
        for (int jn = 0; jn < 8; jn++) {
            int col = bn + wn * 64 + jn * 8 + 2 * tm;
            if (NGUARD && col >= N) continue;
            size_t o0 = (size_t)row * N + col;
            size_t o1 = (size_t)(row + 8) * N + col;
            float v[4] = {acc[im][jn][0], acc[im][jn][1],
                          acc[im][jn][2], acc[im][jn][3]};
            if (EPI == 2) {
                float b0 = bias[col], b1 = bias[col + 1];
                v[0] += b0; v[1] += b1; v[2] += b0; v[3] += b1;
                #pragma unroll
                for (int e = 0; e < 4; e++)
                    v[e] = (v[e] > 20.f) ? v[e] : log1pf(__expf(v[e]));
            } else if (EPI == 1) {
                if (col >= half_n) {
                    #pragma unroll
                    for (int e = 0; e < 4; e++)
                        v[e] = v[e] / (1.f + __expf(-v[e]));
                }
            }
            if (resid) {
                float2 r0 = *(const float2*)(resid + o0);
                float2 r1 = *(const float2*)(resid + o1);
                v[0] += r0.x; v[1] += r0.y;
                v[2] += r1.x; v[3] += r1.y;
            }
            if (OUT == 0 || OUT == 2) {
                *(float2*)(C + o0) = make_float2(v[0], v[1]);
                *(float2*)(C + o1) = make_float2(v[2], v[3]);
            }
            if (OUT == 1 || OUT == 2) {
                *(__half2*)(Ch + o0) = __floats2half2_rn(v[0], v[1]);
                *(__half2*)(Ch + o1) = __floats2half2_rn(v[2], v[3]);
            }
        }
    }
}

// ---------------- 3. depthwise causal conv + bias + SiLU (half2) ------------
__global__ void conv_silu_kernel(const float* __restrict__ cw,
                                 const float* __restrict__ cb) {
    int idx = blockIdx.x * blockDim.x + threadIdx.x;   // over NTOK * 1024 pairs
    if (idx >= NTOK * (D_INNER / 2)) return;
    int dp = idx & (D_INNER / 2 - 1);
    int d = dp * 2;
    int tok = idx >> 10;
    int t = tok & (T_SZ - 1);
    float a0 = cb[d], a1 = cb[d + 1];
    #pragma unroll
    for (int k = 0; k < D_CONV; ++k) {
        int tt = t - (D_CONV - 1) + k;
        if (tt >= 0) {
            __half2 v = *(const __half2*)(g_xr_h +
                (size_t)(tok - (D_CONV - 1) + k) * (2 * D_INNER) + d);
            float2 vf = __half22float2(v);
            a0 = fmaf(vf.x, cw[d * D_CONV + k], a0);
            a1 = fmaf(vf.y, cw[(d + 1) * D_CONV + k], a1);
        }
    }
    a0 = a0 / (1.f + __expf(-a0));
    a1 = a1 / (1.f + __expf(-a1));
    *(__half2*)(g_u_h + (size_t)tok * D_INNER + d) = __floats2half2_rn(a0, a1);
}

// ---------------- 6. smem-staged selective scan ------------------------------
#define SCAN_TC 32
#define SCAN_CH 32
#define SCAN_NC (T_SZ / SCAN_TC)

__global__ __launch_bounds__(512, 1)
void scan_kernel(const float* __restrict__ A_log, const float* __restrict__ Dp) {
    __shared__ float  sD[2][SCAN_TC][SCAN_CH];
    __shared__ __half sU[2][SCAN_TC][SCAN_CH];
    __shared__ __half sR[2][SCAN_TC][SCAN_CH];
    __shared__ float  sBC[2][SCAN_TC][32];
    __shared__ float  sY[SCAN_TC][SCAN_CH];

    int tid = threadIdx.x;
    int bb = blockIdx.x >> 6;
    int d0 = (blockIdx.x & 63) * SCAN_CH;
    size_t tokbase = (size_t)bb * T_SZ;

    int li = (tid & 255) >> 3;
    int lj = ((tid & 255) & 7) << 2;

    int warp = tid >> 5, lane = tid & 31;
    int ch = warp * 2 + (lane >> 4);
    int n = lane & 15;
    int dg = d0 + ch;
    float a = -__expf(A_log[dg * D_STATE + n]);
    float Dv = Dp[dg];
    float h = 0.f;

    auto issue_chunk = [&](int c, int buf) {
        size_t t0 = tokbase + (size_t)c * SCAN_TC;
        if (tid < 256) {
            int r = tid >> 3, c4 = (tid & 7) << 2;
            cpa16((uint32_t)__cvta_generic_to_shared(&sD[buf][r][c4]),
                  g_delta + (t0 + r) * D_INNER + d0 + c4);
            if (tid < 128) {
                int r2 = tid >> 2, c8 = (tid & 3) << 3;
                cpa16((uint32_t)__cvta_generic_to_shared(&sU[buf][r2][c8]),
                      g_u_h + (t0 + r2) * D_INNER + d0 + c8);
            } else {
                int id = tid - 128;
                int r2 = id >> 2, c8 = (id & 3) << 3;
                cpa16((uint32_t)__cvta_generic_to_shared(&sR[buf][r2][c8]),
                      g_xr_h + (t0 + r2) * (2 * D_INNER) + D_INNER + d0 + c8);
            }
        } else {
            int id = tid - 256;
            int r = id >> 3, c4 = (id & 7) << 2;
            cpa16((uint32_t)__cvta_generic_to_shared(&sBC[buf][r][c4]),
                  g_xdbc + (t0 + r) * XDBC_W + DT_RANK + c4);
        }
        cpa_commit();
    };

    issue_chunk(0, 0);

    for (int c = 0; c < SCAN_NC; ++c) {
        int buf = c & 1;
        if (c + 1 < SCAN_NC) {
            issue_chunk(c + 1, buf ^ 1);
            cpa_wait<1>();
        } else {
            cpa_wait<0>();
        }
        __syncthreads();

        #pragma unroll 4
        for (int t = 0; t < SCAN_TC; ++t) {
            float dv = sD[buf][t][ch];
            float uv = __half2float(sU[buf][t][ch]);
            float Bv = sBC[buf][t][n];
            float Cv = sBC[buf][t][16 + n];
            h = fmaf(__expf(dv * a), h, (dv * uv) * Bv);
            float p = h * Cv;
            p += __shfl_down_sync(0xffffffffu, p, 8, 16);
            p += __shfl_down_sync(0xffffffffu, p, 4, 16);
            p += __shfl_down_sync(0xffffffffu, p, 2, 16);
            p += __shfl_down_sync(0xffffffffu, p, 1, 16);
            if (n == 0) {
                sY[t][ch] = fmaf(uv, Dv, p) * __half2float(sR[buf][t][ch]);
            }
        }
        __syncthreads();

        if (tid < 256) {
            size_t tok = tokbase + (size_t)c * SCAN_TC + li;
            float4 v = *(float4*)(&sY[li][lj]);
            __half* dst = g_y_h + tok * D_INNER + d0 + lj;
            *(__half2*)(dst) = __floats2half2_rn(v.x, v.y);
            *(__half2*)(dst + 2) = __floats2half2_rn(v.z, v.w);
        }
    }
}

// ---------------- launch ----------------------------------------------------
extern "C" void kernel_launch(void* const* d_in, const int* in_sizes, int n_in,
                              void* d_out, int out_size) {
    const float* x      = (const float*)d_in[0];
    const float* norm_w = (const float*)d_in[1];
    const float* w_in   = (const float*)d_in[2];
    const float* conv_w = (const float*)d_in[3];
    const float* conv_b = (const float*)d_in[4];
    const float* w_x    = (const float*)d_in[5];
    const float* w_dt   = (const float*)d_in[6];
    const float* b_dt   = (const float*)d_in[7];
    const float* A_log  = (const float*)d_in[8];
    const float* Dp     = (const float*)d_in[9];
    const float* w_out  = (const float*)d_in[10];
    float* out = (float*)d_out;

    void *p_xn_h, *p_xr_h, *p_u_h, *p_xdbc, *p_xdbc_h, *p_delta, *p_y_h;
    void *p_winT, *p_wxT, *p_wdtT, *p_woutT;
    cudaGetSymbolAddress(&p_xn_h, g_xn_h);
    cudaGetSymbolAddress(&p_xr_h, g_xr_h);
    cudaGetSymbolAddress(&p_u_h, g_u_h);
    cudaGetSymbolAddress(&p_xdbc, g_xdbc);
    cudaGetSymbolAddress(&p_xdbc_h, g_xdbc_h);
    cudaGetSymbolAddress(&p_delta, g_delta);
    cudaGetSymbolAddress(&p_y_h, g_y_h);
    cudaGetSymbolAddress(&p_winT, g_winT);
    cudaGetSymbolAddress(&p_wxT, g_wxT);
    cudaGetSymbolAddress(&p_wdtT, g_wdtT);
    cudaGetSymbolAddress(&p_woutT, g_woutT);

    dim3 tb(32, 8);
    transpose_h<<<dim3(2 * D_INNER / 32, D_MODEL / 32), tb>>>(
        w_in, (__half*)p_winT, D_MODEL, 2 * D_INNER);
    transpose_h<<<dim3(128 / 32, D_INNER / 32), tb>>>(
        w_x, (__half*)p_wxT, D_INNER, XDBC_W);
    transpose_h<<<dim3(D_INNER / 32, DT_RANK / 32), tb>>>(
        w_dt, (__half*)p_wdtT, DT_RANK, D_INNER);
    transpose_h<<<dim3(D_MODEL / 32, D_INNER / 32), tb>>>(
        w_out, (__half*)p_woutT, D_INNER, D_MODEL);

    rmsnorm_kernel<<<NTOK, 256>>>(x, norm_w);

    // xr_h = [xn @ w_in] with silu on res half — fp16 out only
    gemm_h16<false, 1, 1><<<dim3(2 * D_INNER / 128, NTOK / 128), 128>>>(
        (const __half*)p_xn_h, (const __half*)p_winT, nullptr, nullptr,
        nullptr, (__half*)p_xr_h, NTOK, 2 * D_INNER, D_MODEL, D_MODEL);

    conv_silu_kernel<<<(NTOK * D_INNER / 2 + 255) / 256, 256>>>(conv_w, conv_b);

    // xdbc = u @ w_x  (N=96; fp32 for scan B/C + fp16 for delta GEMM)
    gemm_h16<true, 0, 2><<<dim3(1, NTOK / 128), 128>>>(
        (const __half*)p_u_h, (const __half*)p_wxT, nullptr, nullptr,
        (float*)p_xdbc, (__half*)p_xdbc_h, NTOK, XDBC_W, D_INNER, D_INNER);

    // delta = softplus(dt @ w_dt + b_dt)  (K=64, A lda=96) — fp32 out
    gemm_h16<false, 2, 0><<<dim3(D_INNER / 128, NTOK / 128), 128>>>(
        (const __half*)p_xdbc_h, (const __half*)p_wdtT, nullptr, b_dt,
        (float*)p_delta, nullptr, NTOK, D_INNER, DT_RANK, XDBC_W);

    scan_kernel<<<B_SZ * D_INNER / SCAN_CH, 512>>>(A_log, Dp);

    // out = y @ w_out + x  — fp32 out
    gemm_h16<false, 0, 0><<<dim3(D_MODEL / 128, NTOK / 128), 128>>>(
        (const __half*)p_y_h, (const __half*)p_woutT, x, nullptr,
        out, nullptr, NTOK, D_MODEL, D_INNER, D_INNER);
}